// round 12
// baseline (speedup 1.0000x reference)
#include <cuda_runtime.h>
#include <cuda_bf16.h>
#include <cstdint>

#define SEQ     512
#define INP     5
#define HID     64
#define NB      56          // batch cols per CTA
#define NTL     7           // n-tiles (8 cols each)
#define KT16    4           // full k16 tiles (k=0..63)
#define BPAD    88          // bf16 per B column (44 words = 12 mod 32: conflict-free)
#define THREADS 256

struct SmemT {
    __align__(16) __nv_bfloat16 B[2][2][NB * BPAD];  // [parity][0=hi,1=lo][col][k]
};

__device__ __forceinline__ uint32_t pack_bf16(float lo, float hi) {
    __nv_bfloat162 t = __floats2bfloat162_rn(lo, hi);   // .x=lo (lower 16 bits)
    return *(uint32_t*)&t;
}
__device__ __forceinline__ void split2(float v, float& hi, float& lo) {
    hi = __bfloat162float(__float2bfloat16(v));
    lo = v - hi;
}

// Hardware tanh (sm_75+), volatile: placement pinned in program order so the
// hand interleave with MMA groups survives into SASS.
__device__ __forceinline__ float tanh_v(float x) {
    float y;
    asm volatile("tanh.approx.f32 %0, %1;" : "=f"(y) : "f"(x));
    return y;
}

// mma.sync m16n8k16 row.col bf16 -> f32, D += A*B
__device__ __forceinline__ void mma16816(float* c, const uint32_t* a, const uint32_t* b) {
    asm volatile(
        "mma.sync.aligned.m16n8k16.row.col.f32.bf16.bf16.f32 "
        "{%0,%1,%2,%3}, {%4,%5,%6,%7}, {%8,%9}, {%0,%1,%2,%3};"
        : "+f"(c[0]), "+f"(c[1]), "+f"(c[2]), "+f"(c[3])
        : "r"(a[0]), "r"(a[1]), "r"(a[2]), "r"(a[3]), "r"(b[0]), "r"(b[1]));
}
// mma.sync m16n8k8 row.col bf16 -> f32, D += A*B (K-tail tile)
__device__ __forceinline__ void mma1688(float* c, const uint32_t* a, uint32_t b) {
    asm volatile(
        "mma.sync.aligned.m16n8k8.row.col.f32.bf16.bf16.f32 "
        "{%0,%1,%2,%3}, {%4,%5}, {%6}, {%0,%1,%2,%3};"
        : "+f"(c[0]), "+f"(c[1]), "+f"(c[2]), "+f"(c[3])
        : "r"(a[0]), "r"(a[1]), "r"(b));
}

// Extended weight matrix element: W_ext[m][k], m permuted so that within a
// warp's m-pair (tiles 2w, 2w+1) each thread's 4 C rows = i,f,g,o of one j.
//   j = (m>>5)*8 + (m&7),  g = 2*((m>>4)&1) + ((m>>3)&1)
__device__ float wext(const float* W_hh, const float* W_ih,
                      const float* b_ih, const float* b_hh, int m, int k) {
    int j   = ((m >> 5) << 3) | (m & 7);
    int g   = (((m >> 4) & 1) << 1) | ((m >> 3) & 1);
    int row = g * HID + j;
    if (k < HID)            return W_hh[row * HID + k];
    if (k < HID + INP)      return W_ih[row * INP + (k - HID)];
    if (k == HID + INP)     return b_ih[row] + b_hh[row];   // bias column
    return 0.f;
}

// ---------------------------------------------------------------------------
// HMMA LSTM (verified R9 structure). Single delta: epilogue(nt-1) is split
// into 4 micro-stages emitted BETWEEN the five 6-MMA groups of tile nt's
// burst. Since all MMA/MUFU are asm volatile, source order = SASS order, so
// each epilogue stage executes while >=6 freshly issued HMMAs back-pressure
// the tensor pipe -> the pipe no longer drains during epilogues.
// ---------------------------------------------------------------------------
__global__ void __launch_bounds__(THREADS, 1)
lstm_hmma_kernel(const float* __restrict__ inputs,  // [B, SEQ, INP]
                 const float* __restrict__ W_ih,    // [256, INP]
                 const float* __restrict__ W_hh,    // [256, HID]
                 const float* __restrict__ b_ih,    // [256]
                 const float* __restrict__ b_hh,    // [256]
                 const float* __restrict__ fc_w,    // [1, HID]
                 const float* __restrict__ fc_b,    // [1]
                 float* __restrict__ out,           // [B, 1]
                 int batch)
{
    __shared__ SmemT sm;

    const int t    = threadIdx.x;
    const int lane = t & 31;
    const int w    = t >> 5;
    const int gid  = lane >> 2;          // fragment row group 0..7
    const int tig  = lane & 3;           // fragment col group 0..3
    const int jm   = (w << 3) | gid;     // this thread's hidden index
    const int batch0 = blockIdx.x * NB;

    // ---- init smem: zero all buffers, set bias row (k=69) = 1.0 in hi bufs
    for (int idx = t; idx < 2 * 2 * NB * BPAD / 2; idx += THREADS)
        ((uint32_t*)sm.B)[idx] = 0u;
    __syncthreads();
    if (t < NB) {
        sm.B[0][0][t * BPAD + HID + INP] = __float2bfloat16(1.0f);
        sm.B[1][0][t * BPAD + HID + INP] = __float2bfloat16(1.0f);
    }

    // x(0) into parity-0 buffer rows 64..68
    for (int q = t; q < NB * INP; q += THREADS) {
        int col = q / INP, i = q - col * INP;
        int row = min(batch0 + col, batch - 1);
        float xv = inputs[(size_t)row * (SEQ * INP) + i];
        float xh, xl; split2(xv, xh, xl);
        sm.B[0][0][col * BPAD + HID + i] = __float2bfloat16(xh);
        sm.B[0][1][col * BPAD + HID + i] = __float2bfloat16(xl);
    }

    // ---- load W_ext fragments into registers (hi/lo), one-time
    uint32_t ahi[2][KT16][4], alo[2][KT16][4];   // k16 tiles, k=0..63
    uint32_t ahi8[2][2], alo8[2][2];             // k8 tail, k=64..71
#pragma unroll
    for (int mt = 0; mt < 2; ++mt) {
        const int mbase = ((w << 1) | mt) << 4;
#pragma unroll
        for (int kt = 0; kt < KT16; ++kt) {
#pragma unroll
            for (int cp = 0; cp < 2; ++cp) {          // col pair: k+0/1 or k+8/9
#pragma unroll
                for (int rr = 0; rr < 2; ++rr) {      // row gid or gid+8
                    int m  = mbase + gid + rr * 8;
                    int k0 = kt * 16 + 2 * tig + cp * 8;
                    float v0 = wext(W_hh, W_ih, b_ih, b_hh, m, k0);
                    float v1 = wext(W_hh, W_ih, b_ih, b_hh, m, k0 + 1);
                    float h0, l0, h1, l1;
                    split2(v0, h0, l0);
                    split2(v1, h1, l1);
                    ahi[mt][kt][cp * 2 + rr] = pack_bf16(h0, h1);
                    alo[mt][kt][cp * 2 + rr] = pack_bf16(l0, l1);
                }
            }
        }
        // k8 tail: k = 64 + 2*tig (+1)
#pragma unroll
        for (int rr = 0; rr < 2; ++rr) {
            int m  = mbase + gid + rr * 8;
            int k0 = 64 + 2 * tig;
            float v0 = wext(W_hh, W_ih, b_ih, b_hh, m, k0);
            float v1 = wext(W_hh, W_ih, b_ih, b_hh, m, k0 + 1);
            float h0, l0, h1, l1;
            split2(v0, h0, l0);
            split2(v1, h1, l1);
            ahi8[mt][rr] = pack_bf16(h0, h1);
            alo8[mt][rr] = pack_bf16(l0, l1);
        }
    }

    // x prefetch ownership: indices t and t+256 (< NB*INP = 280)
    const int  q1   = t + THREADS;
    const bool hq1  = q1 < NB * INP;
    const int  c0i  = t / INP,  i0 = t - c0i * INP;
    const int  c1i  = hq1 ? q1 / INP : 0, i1 = hq1 ? q1 - c1i * INP : 0;
    const float* xp0 = inputs + (size_t)min(batch0 + c0i, batch - 1) * (SEQ * INP) + i0;
    const float* xp1 = inputs + (size_t)min(batch0 + c1i, batch - 1) * (SEQ * INP) + i1;

    float cst[2 * NTL];
#pragma unroll
    for (int q = 0; q < 2 * NTL; ++q) cst[q] = 0.f;

    __syncthreads();

    for (int s = 0; s < SEQ; ++s) {
        // prefetch next x
        float xv0 = 0.f, xv1 = 0.f;
        const bool dox = (s + 1 < SEQ);
        if (dox) {
            xv0 = __ldg(xp0 + (size_t)(s + 1) * INP);
            if (hq1) xv1 = __ldg(xp1 + (size_t)(s + 1) * INP);
        }

        const __nv_bfloat16* BH = sm.B[s & 1][0];
        const __nv_bfloat16* BL = sm.B[s & 1][1];
        __nv_bfloat16* WH = sm.B[(s + 1) & 1][0];
        __nv_bfloat16* WL = sm.B[(s + 1) & 1][1];

        float cacc[2][NTL][4];
        float act[2][4];    // in-flight activations for the cell being retired

        // B fragments, double-buffered across n-tiles
        uint32_t bh[2][KT16][2], bl[2][KT16][2], b8h[2], b8l[2];

#define LOADFRAG(buf, nt)                                                     \
        {                                                                     \
            const int ncol = (nt) * 8 + gid;                                  \
            const uint32_t* colH = (const uint32_t*)(BH + ncol * BPAD);       \
            const uint32_t* colL = (const uint32_t*)(BL + ncol * BPAD);       \
            _Pragma("unroll")                                                 \
            for (int kt = 0; kt < KT16; ++kt) {                               \
                bh[buf][kt][0] = colH[kt * 8 + tig];                          \
                bh[buf][kt][1] = colH[kt * 8 + tig + 4];                      \
                bl[buf][kt][0] = colL[kt * 8 + tig];                          \
                bl[buf][kt][1] = colL[kt * 8 + tig + 4];                      \
            }                                                                 \
            b8h[buf] = colH[32 + tig];                                        \
            b8l[buf] = colL[32 + tig];                                        \
        }

        // Epilogue micro-stage A: activations for cell q of tile nt (4 MUFU)
#define EPI_A(nt, q)                                                          \
        {                                                                     \
            act[q][0] = tanh_v(0.5f * cacc[0][nt][q]);        /* i */         \
            act[q][1] = tanh_v(0.5f * cacc[0][nt][2 + q]);    /* f */         \
            act[q][2] = tanh_v(cacc[1][nt][q]);               /* g */         \
            act[q][3] = tanh_v(0.5f * cacc[1][nt][2 + q]);    /* o */         \
        }
        // Epilogue micro-stage B: c/h update + STS for cell q of tile nt
#define EPI_B(nt, q)                                                          \
        {                                                                     \
            const float ig = fmaf(act[q][0], 0.5f, 0.5f);                     \
            const float fg = fmaf(act[q][1], 0.5f, 0.5f);                     \
            const float og = fmaf(act[q][3], 0.5f, 0.5f);                     \
            const int  ci = (nt) * 2 + (q);                                   \
            const float cn = fg * cst[ci] + ig * act[q][2];                   \
            cst[ci] = cn;                                                     \
            const float hv = og * tanh_v(cn);                                 \
            float hh, hl; split2(hv, hh, hl);                                 \
            const int col = (nt) * 8 + 2 * tig + (q);                         \
            WH[col * BPAD + jm] = __float2bfloat16(hh);                       \
            WL[col * BPAD + jm] = __float2bfloat16(hl);                       \
        }

        // One 6-MMA group (k16 tile kt) for tile nt, fragments in buf
#define MMAGRP(nt, buf, kt)                                                   \
        {                                                                     \
            mma16816(cacc[0][nt], ahi[0][kt], bh[buf][kt]);                   \
            mma16816(cacc[1][nt], ahi[1][kt], bh[buf][kt]);                   \
            mma16816(cacc[0][nt], ahi[0][kt], bl[buf][kt]);                   \
            mma16816(cacc[1][nt], ahi[1][kt], bl[buf][kt]);                   \
            mma16816(cacc[0][nt], alo[0][kt], bh[buf][kt]);                   \
            mma16816(cacc[1][nt], alo[1][kt], bh[buf][kt]);                   \
        }
#define MMAGRP8(nt, buf)                                                      \
        {                                                                     \
            mma1688(cacc[0][nt], ahi8[0], b8h[buf]);                          \
            mma1688(cacc[1][nt], ahi8[1], b8h[buf]);                          \
            mma1688(cacc[0][nt], ahi8[0], b8l[buf]);                          \
            mma1688(cacc[1][nt], ahi8[1], b8l[buf]);                          \
            mma1688(cacc[0][nt], alo8[0], b8h[buf]);                          \
            mma1688(cacc[1][nt], alo8[1], b8h[buf]);                          \
        }

        LOADFRAG(0, 0);
#pragma unroll
        for (int nt = 0; nt < NTL; ++nt) {
            const int cur = nt & 1, nxt = cur ^ 1;
            if (nt + 1 < NTL) LOADFRAG(nxt, nt + 1);

#pragma unroll
            for (int mt = 0; mt < 2; ++mt)
#pragma unroll
                for (int q = 0; q < 4; ++q) cacc[mt][nt][q] = 0.f;

            // interleave: epilogue(nt-1) micro-stages between the MMA groups
            MMAGRP(nt, cur, 0);
            if (nt > 0) EPI_A(nt - 1, 0);
            MMAGRP(nt, cur, 1);
            if (nt > 0) EPI_B(nt - 1, 0);
            MMAGRP(nt, cur, 2);
            if (nt > 0) EPI_A(nt - 1, 1);
            MMAGRP(nt, cur, 3);
            if (nt > 0) EPI_B(nt - 1, 1);
            MMAGRP8(nt, cur);
        }
        // tail: epilogue for the last tile (exposed; ~150 cyc)
        EPI_A(NTL - 1, 0);
        EPI_B(NTL - 1, 0);
        EPI_A(NTL - 1, 1);
        EPI_B(NTL - 1, 1);
#undef EPI_A
#undef EPI_B
#undef MMAGRP
#undef MMAGRP8
#undef LOADFRAG

        // stash next x into next-parity buffer
        if (dox) {
            float xh, xl;
            split2(xv0, xh, xl);
            WH[c0i * BPAD + HID + i0] = __float2bfloat16(xh);
            WL[c0i * BPAD + HID + i0] = __float2bfloat16(xl);
            if (hq1) {
                split2(xv1, xh, xl);
                WH[c1i * BPAD + HID + i1] = __float2bfloat16(xh);
                WL[c1i * BPAD + HID + i1] = __float2bfloat16(xl);
            }
        }
        __syncthreads();
    }

    // ---- final FC + leaky ReLU; h(512) is in parity-0 buffer (hi+lo)
    const __nv_bfloat16* FH = sm.B[0][0];
    const __nv_bfloat16* FL = sm.B[0][1];
    const float fw0 = fc_w[lane], fw1 = fc_w[lane + 32];
    const float fb  = fc_b[0];
#pragma unroll
    for (int q = 0; q < NTL; ++q) {
        const int col = w * NTL + q;
        float hA = __bfloat162float(FH[col * BPAD + lane])
                 + __bfloat162float(FL[col * BPAD + lane]);
        float hB = __bfloat162float(FH[col * BPAD + lane + 32])
                 + __bfloat162float(FL[col * BPAD + lane + 32]);
        float p = hA * fw0 + hB * fw1;
#pragma unroll
        for (int off = 16; off > 0; off >>= 1)
            p += __shfl_xor_sync(0xffffffffu, p, off);
        if (lane == 0) {
            const int row = batch0 + col;
            if (row < batch) {
                const float v = p + fb;
                out[row] = (v >= 0.f) ? v : 0.01f * v;
            }
        }
    }
}

extern "C" void kernel_launch(void* const* d_in, const int* in_sizes, int n_in,
                              void* d_out, int out_size) {
    const float* inputs = (const float*)d_in[0];
    const float* W_ih   = (const float*)d_in[1];
    const float* W_hh   = (const float*)d_in[2];
    const float* b_ih   = (const float*)d_in[3];
    const float* b_hh   = (const float*)d_in[4];
    const float* fc_w   = (const float*)d_in[5];
    const float* fc_b   = (const float*)d_in[6];
    float*       out    = (float*)d_out;

    const int batch = in_sizes[0] / (SEQ * INP);      // 8192
    const int grid  = (batch + NB - 1) / NB;          // 147

    lstm_hmma_kernel<<<grid, THREADS>>>(inputs, W_ih, W_hh, b_ih, b_hh,
                                        fc_w, fc_b, out, batch);
}

// round 13
// speedup vs baseline: 1.4464x; 1.4464x over previous
#include <cuda_runtime.h>
#include <cuda_fp16.h>
#include <cstdint>

#define SEQ     512
#define INP     5
#define HID     64
#define NB      56          // batch cols per CTA
#define NTL     7           // n-tiles (8 cols each)
#define KT16    4           // full k16 tiles (k=0..63)
#define BPAD    88          // fp16 per B column (44 words = 12 mod 32: conflict-free)
#define THREADS 256

struct SmemT {
    __align__(16) __half B[2][NB * BPAD];  // [parity][col][k] -- single fp16 buffer
};

__device__ __forceinline__ uint32_t pack_h2(__half lo, __half hi) {
    __half2 t = __halves2half2(lo, hi);    // .x = lo (lower 16 bits) = smaller k
    return *(uint32_t*)&t;
}

// Hardware tanh (sm_75+): 1 MUFU op, max err ~1e-4 abs
__device__ __forceinline__ float tanh_hw(float x) {
    float y;
    asm("tanh.approx.f32 %0, %1;" : "=f"(y) : "f"(x));
    return y;
}
__device__ __forceinline__ float sigmoid_f(float x) {
    return fmaf(tanh_hw(0.5f * x), 0.5f, 0.5f);
}
__device__ __forceinline__ float tanh_f(float x) { return tanh_hw(x); }

// mma.sync m16n8k16 row.col fp16 -> f32, D += A*B
__device__ __forceinline__ void mma16816(float* c, const uint32_t* a, const uint32_t* b) {
    asm volatile(
        "mma.sync.aligned.m16n8k16.row.col.f32.f16.f16.f32 "
        "{%0,%1,%2,%3}, {%4,%5,%6,%7}, {%8,%9}, {%0,%1,%2,%3};"
        : "+f"(c[0]), "+f"(c[1]), "+f"(c[2]), "+f"(c[3])
        : "r"(a[0]), "r"(a[1]), "r"(a[2]), "r"(a[3]), "r"(b[0]), "r"(b[1]));
}
// mma.sync m16n8k8 row.col fp16 -> f32, D += A*B (K-tail tile)
__device__ __forceinline__ void mma1688(float* c, const uint32_t* a, uint32_t b) {
    asm volatile(
        "mma.sync.aligned.m16n8k8.row.col.f32.f16.f16.f32 "
        "{%0,%1,%2,%3}, {%4,%5}, {%6}, {%0,%1,%2,%3};"
        : "+f"(c[0]), "+f"(c[1]), "+f"(c[2]), "+f"(c[3])
        : "r"(a[0]), "r"(a[1]), "r"(b));
}

// Extended weight matrix element: W_ext[m][k], m permuted so that within a
// warp's m-pair (tiles 2w, 2w+1) each thread's 4 C rows = i,f,g,o of one j.
//   j = (m>>5)*8 + (m&7),  g = 2*((m>>4)&1) + ((m>>3)&1)
__device__ float wext(const float* W_hh, const float* W_ih,
                      const float* b_ih, const float* b_hh, int m, int k) {
    int j   = ((m >> 5) << 3) | (m & 7);
    int g   = (((m >> 4) & 1) << 1) | ((m >> 3) & 1);
    int row = g * HID + j;
    if (k < HID)            return W_hh[row * HID + k];
    if (k < HID + INP)      return W_ih[row * INP + (k - HID)];
    if (k == HID + INP)     return b_ih[row] + b_hh[row];   // bias column
    return 0.f;
}

// ---------------------------------------------------------------------------
// HMMA LSTM (verified R9 structure). Delta: fp16 operands with 2-term split.
//   W = Whi(fp16) + Wlo(fp16)   (error ~2^-22)
//   h, x stored as single fp16  (error ~2^-11)
//   gates = Whi*B + Wlo*B       (2 MMA terms, was 3; B traffic halved)
// fp32 accumulate throughout; activations exact-path fp32 as before.
// ---------------------------------------------------------------------------
__global__ void __launch_bounds__(THREADS, 1)
lstm_hmma_kernel(const float* __restrict__ inputs,  // [B, SEQ, INP]
                 const float* __restrict__ W_ih,    // [256, INP]
                 const float* __restrict__ W_hh,    // [256, HID]
                 const float* __restrict__ b_ih,    // [256]
                 const float* __restrict__ b_hh,    // [256]
                 const float* __restrict__ fc_w,    // [1, HID]
                 const float* __restrict__ fc_b,    // [1]
                 float* __restrict__ out,           // [B, 1]
                 int batch)
{
    __shared__ SmemT sm;

    const int t    = threadIdx.x;
    const int lane = t & 31;
    const int w    = t >> 5;
    const int gid  = lane >> 2;          // fragment row group 0..7
    const int tig  = lane & 3;           // fragment col group 0..3
    const int jm   = (w << 3) | gid;     // this thread's hidden index
    const int batch0 = blockIdx.x * NB;

    // ---- init smem: zero both buffers, set bias row (k=69) = 1.0
    for (int idx = t; idx < 2 * NB * BPAD / 2; idx += THREADS)
        ((uint32_t*)sm.B)[idx] = 0u;
    __syncthreads();
    if (t < NB) {
        sm.B[0][t * BPAD + HID + INP] = __float2half(1.0f);
        sm.B[1][t * BPAD + HID + INP] = __float2half(1.0f);
    }

    // x(0) into parity-0 buffer rows 64..68
    for (int q = t; q < NB * INP; q += THREADS) {
        int col = q / INP, i = q - col * INP;
        int row = min(batch0 + col, batch - 1);
        sm.B[0][col * BPAD + HID + i] =
            __float2half(inputs[(size_t)row * (SEQ * INP) + i]);
    }

    // ---- load W_ext fragments into registers (fp16 hi/lo split), one-time
    uint32_t ahi[2][KT16][4], alo[2][KT16][4];   // k16 tiles, k=0..63
    uint32_t ahi8[2][2], alo8[2][2];             // k8 tail, k=64..71
#pragma unroll
    for (int mt = 0; mt < 2; ++mt) {
        const int mbase = ((w << 1) | mt) << 4;
#pragma unroll
        for (int kt = 0; kt < KT16; ++kt) {
#pragma unroll
            for (int cp = 0; cp < 2; ++cp) {          // col pair: k+0/1 or k+8/9
#pragma unroll
                for (int rr = 0; rr < 2; ++rr) {      // row gid or gid+8
                    int m  = mbase + gid + rr * 8;
                    int k0 = kt * 16 + 2 * tig + cp * 8;
                    float v0 = wext(W_hh, W_ih, b_ih, b_hh, m, k0);
                    float v1 = wext(W_hh, W_ih, b_ih, b_hh, m, k0 + 1);
                    __half h0 = __float2half(v0);
                    __half h1 = __float2half(v1);
                    __half l0 = __float2half(v0 - __half2float(h0));
                    __half l1 = __float2half(v1 - __half2float(h1));
                    ahi[mt][kt][cp * 2 + rr] = pack_h2(h0, h1);
                    alo[mt][kt][cp * 2 + rr] = pack_h2(l0, l1);
                }
            }
        }
        // k8 tail: k = 64 + 2*tig (+1)
#pragma unroll
        for (int rr = 0; rr < 2; ++rr) {
            int m  = mbase + gid + rr * 8;
            int k0 = 64 + 2 * tig;
            float v0 = wext(W_hh, W_ih, b_ih, b_hh, m, k0);
            float v1 = wext(W_hh, W_ih, b_ih, b_hh, m, k0 + 1);
            __half h0 = __float2half(v0);
            __half h1 = __float2half(v1);
            __half l0 = __float2half(v0 - __half2float(h0));
            __half l1 = __float2half(v1 - __half2float(h1));
            ahi8[mt][rr] = pack_h2(h0, h1);
            alo8[mt][rr] = pack_h2(l0, l1);
        }
    }

    // x prefetch ownership: indices t and t+256 (< NB*INP = 280)
    const int  q1   = t + THREADS;
    const bool hq1  = q1 < NB * INP;
    const int  c0i  = t / INP,  i0 = t - c0i * INP;
    const int  c1i  = hq1 ? q1 / INP : 0, i1 = hq1 ? q1 - c1i * INP : 0;
    const float* xp0 = inputs + (size_t)min(batch0 + c0i, batch - 1) * (SEQ * INP) + i0;
    const float* xp1 = inputs + (size_t)min(batch0 + c1i, batch - 1) * (SEQ * INP) + i1;

    float cst[2 * NTL];
#pragma unroll
    for (int q = 0; q < 2 * NTL; ++q) cst[q] = 0.f;

    __syncthreads();

    for (int s = 0; s < SEQ; ++s) {
        // prefetch next x
        float xv0 = 0.f, xv1 = 0.f;
        const bool dox = (s + 1 < SEQ);
        if (dox) {
            xv0 = __ldg(xp0 + (size_t)(s + 1) * INP);
            if (hq1) xv1 = __ldg(xp1 + (size_t)(s + 1) * INP);
        }

        const __half* BH = sm.B[s & 1];
        __half*       WB = sm.B[(s + 1) & 1];

        float cacc[2][NTL][4];

        // B fragments, double-buffered across n-tiles
        uint32_t bh[2][KT16][2], b8h[2];

#define LOADFRAG(buf, nt)                                                     \
        {                                                                     \
            const int ncol = (nt) * 8 + gid;                                  \
            const uint32_t* colH = (const uint32_t*)(BH + ncol * BPAD);       \
            _Pragma("unroll")                                                 \
            for (int kt = 0; kt < KT16; ++kt) {                               \
                bh[buf][kt][0] = colH[kt * 8 + tig];                          \
                bh[buf][kt][1] = colH[kt * 8 + tig + 4];                      \
            }                                                                 \
            b8h[buf] = colH[32 + tig];                                        \
        }

        // Epilogue for one n-tile: cells (j=jm, col = nt*8 + 2tig + q)
#define EPILOGUE(nt)                                                          \
        {                                                                     \
            _Pragma("unroll")                                                 \
            for (int q = 0; q < 2; ++q) {                                     \
                const float gi = cacc[0][nt][q];                              \
                const float gf = cacc[0][nt][2 + q];                          \
                const float gg = cacc[1][nt][q];                              \
                const float go = cacc[1][nt][2 + q];                          \
                const float ig = sigmoid_f(gi);                               \
                const float fg = sigmoid_f(gf);                               \
                const float gt = tanh_f(gg);                                  \
                const float og = sigmoid_f(go);                               \
                const int  ci = (nt) * 2 + q;                                 \
                const float cn = fg * cst[ci] + ig * gt;                      \
                cst[ci] = cn;                                                 \
                const float hv = og * tanh_f(cn);                             \
                const int col = (nt) * 8 + 2 * tig + q;                       \
                WB[col * BPAD + jm] = __float2half(hv);                       \
            }                                                                 \
        }

        LOADFRAG(0, 0);
#pragma unroll
        for (int nt = 0; nt < NTL; ++nt) {
            const int cur = nt & 1, nxt = cur ^ 1;
            // pipeline: next tile's LDS issue before this tile's MMA burst
            if (nt + 1 < NTL) LOADFRAG(nxt, nt + 1);

#pragma unroll
            for (int mt = 0; mt < 2; ++mt)
#pragma unroll
                for (int q = 0; q < 4; ++q) cacc[mt][nt][q] = 0.f;

            // 2-term fp16: Whi*B + Wlo*B; mt-interleaved (2 chains, in-pipe
            // accumulation handles same-chain dependence at full rate)
#pragma unroll
            for (int kt = 0; kt < KT16; ++kt) {
                mma16816(cacc[0][nt], ahi[0][kt], bh[cur][kt]);
                mma16816(cacc[1][nt], ahi[1][kt], bh[cur][kt]);
                mma16816(cacc[0][nt], alo[0][kt], bh[cur][kt]);
                mma16816(cacc[1][nt], alo[1][kt], bh[cur][kt]);
            }
            mma1688(cacc[0][nt], ahi8[0], b8h[cur]);
            mma1688(cacc[1][nt], ahi8[1], b8h[cur]);
            mma1688(cacc[0][nt], alo8[0], b8h[cur]);
            mma1688(cacc[1][nt], alo8[1], b8h[cur]);

            if (nt > 0) EPILOGUE(nt - 1);
        }
        EPILOGUE(NTL - 1);
#undef EPILOGUE
#undef LOADFRAG

        // stash next x into next-parity buffer
        if (dox) {
            WB[c0i * BPAD + HID + i0] = __float2half(xv0);
            if (hq1) WB[c1i * BPAD + HID + i1] = __float2half(xv1);
        }
        __syncthreads();
    }

    // ---- final FC + leaky ReLU; h(512) is in parity-0 buffer
    const __half* FH = sm.B[0];
    const float fw0 = fc_w[lane], fw1 = fc_w[lane + 32];
    const float fb  = fc_b[0];
#pragma unroll
    for (int q = 0; q < NTL; ++q) {
        const int col = w * NTL + q;
        float hA = __half2float(FH[col * BPAD + lane]);
        float hB = __half2float(FH[col * BPAD + lane + 32]);
        float p = hA * fw0 + hB * fw1;
#pragma unroll
        for (int off = 16; off > 0; off >>= 1)
            p += __shfl_xor_sync(0xffffffffu, p, off);
        if (lane == 0) {
            const int row = batch0 + col;
            if (row < batch) {
                const float v = p + fb;
                out[row] = (v >= 0.f) ? v : 0.01f * v;
            }
        }
    }
}

extern "C" void kernel_launch(void* const* d_in, const int* in_sizes, int n_in,
                              void* d_out, int out_size) {
    const float* inputs = (const float*)d_in[0];
    const float* W_ih   = (const float*)d_in[1];
    const float* W_hh   = (const float*)d_in[2];
    const float* b_ih   = (const float*)d_in[3];
    const float* b_hh   = (const float*)d_in[4];
    const float* fc_w   = (const float*)d_in[5];
    const float* fc_b   = (const float*)d_in[6];
    float*       out    = (float*)d_out;

    const int batch = in_sizes[0] / (SEQ * INP);      // 8192
    const int grid  = (batch + NB - 1) / NB;          // 147

    lstm_hmma_kernel<<<grid, THREADS>>>(inputs, W_ih, W_hh, b_ih, b_hh,
                                        fc_w, fc_b, out, batch);
}

// round 14
// speedup vs baseline: 2.2033x; 1.5233x over previous
#include <cuda_runtime.h>
#include <cuda_fp16.h>
#include <cstdint>

#define SEQ     512
#define INP     5
#define HID     64
#define NB      56          // batch cols per CTA
#define NTL     7           // n-tiles (8 cols each)
#define KT16    4           // full k16 tiles (k=0..63)
#define BPAD    88          // fp16 per B column (44 words = 12 mod 32: conflict-free)
#define THREADS 256

struct SmemT {
    __align__(16) __half B[2][NB * BPAD];  // [parity][col][k] -- single fp16 buffer
};

__device__ __forceinline__ uint32_t pack_h2(__half lo, __half hi) {
    __half2 t = __halves2half2(lo, hi);    // .x = lo (lower 16 bits) = smaller k
    return *(uint32_t*)&t;
}

// Hardware tanh (sm_75+): 1 MUFU op, max err ~1e-4 abs
__device__ __forceinline__ float tanh_hw(float x) {
    float y;
    asm("tanh.approx.f32 %0, %1;" : "=f"(y) : "f"(x));
    return y;
}
__device__ __forceinline__ float sigmoid_f(float x) {
    return fmaf(tanh_hw(0.5f * x), 0.5f, 0.5f);
}
__device__ __forceinline__ float tanh_f(float x) { return tanh_hw(x); }

// mma.sync m16n8k16 row.col fp16 -> f32, D += A*B
__device__ __forceinline__ void mma16816(float* c, const uint32_t* a, const uint32_t* b) {
    asm volatile(
        "mma.sync.aligned.m16n8k16.row.col.f32.f16.f16.f32 "
        "{%0,%1,%2,%3}, {%4,%5,%6,%7}, {%8,%9}, {%0,%1,%2,%3};"
        : "+f"(c[0]), "+f"(c[1]), "+f"(c[2]), "+f"(c[3])
        : "r"(a[0]), "r"(a[1]), "r"(a[2]), "r"(a[3]), "r"(b[0]), "r"(b[1]));
}
// mma.sync m16n8k8 row.col fp16 -> f32, D += A*B (K-tail tile)
__device__ __forceinline__ void mma1688(float* c, const uint32_t* a, uint32_t b) {
    asm volatile(
        "mma.sync.aligned.m16n8k8.row.col.f32.f16.f16.f32 "
        "{%0,%1,%2,%3}, {%4,%5}, {%6}, {%0,%1,%2,%3};"
        : "+f"(c[0]), "+f"(c[1]), "+f"(c[2]), "+f"(c[3])
        : "r"(a[0]), "r"(a[1]), "r"(b));
}

// Extended weight matrix element: W_ext[m][k], m permuted so that within a
// warp's m-pair (tiles 2w, 2w+1) each thread's 4 C rows = i,f,g,o of one j.
//   j = (m>>5)*8 + (m&7),  g = 2*((m>>4)&1) + ((m>>3)&1)
__device__ float wext(const float* W_hh, const float* W_ih,
                      const float* b_ih, const float* b_hh, int m, int k) {
    int j   = ((m >> 5) << 3) | (m & 7);
    int g   = (((m >> 4) & 1) << 1) | ((m >> 3) & 1);
    int row = g * HID + j;
    if (k < HID)            return W_hh[row * HID + k];
    if (k < HID + INP)      return W_ih[row * INP + (k - HID)];
    if (k == HID + INP)     return b_ih[row] + b_hh[row];   // bias column
    return 0.f;
}

// ---------------------------------------------------------------------------
// HMMA LSTM (verified R13 structure). Single delta vs R13: the W-lo split
// term is dropped -> 1-term fp16 MMA (W and h both single fp16, ~2^-11 rel
// quantization each; fp32 accumulate). Calibrated error model predicts
// rel_err ~2e-4 (was 1.03e-4), 5x under threshold. MMA work halves.
// ---------------------------------------------------------------------------
__global__ void __launch_bounds__(THREADS, 1)
lstm_hmma_kernel(const float* __restrict__ inputs,  // [B, SEQ, INP]
                 const float* __restrict__ W_ih,    // [256, INP]
                 const float* __restrict__ W_hh,    // [256, HID]
                 const float* __restrict__ b_ih,    // [256]
                 const float* __restrict__ b_hh,    // [256]
                 const float* __restrict__ fc_w,    // [1, HID]
                 const float* __restrict__ fc_b,    // [1]
                 float* __restrict__ out,           // [B, 1]
                 int batch)
{
    __shared__ SmemT sm;

    const int t    = threadIdx.x;
    const int lane = t & 31;
    const int w    = t >> 5;
    const int gid  = lane >> 2;          // fragment row group 0..7
    const int tig  = lane & 3;           // fragment col group 0..3
    const int jm   = (w << 3) | gid;     // this thread's hidden index
    const int batch0 = blockIdx.x * NB;

    // ---- init smem: zero both buffers, set bias row (k=69) = 1.0
    for (int idx = t; idx < 2 * NB * BPAD / 2; idx += THREADS)
        ((uint32_t*)sm.B)[idx] = 0u;
    __syncthreads();
    if (t < NB) {
        sm.B[0][t * BPAD + HID + INP] = __float2half(1.0f);
        sm.B[1][t * BPAD + HID + INP] = __float2half(1.0f);
    }

    // x(0) into parity-0 buffer rows 64..68
    for (int q = t; q < NB * INP; q += THREADS) {
        int col = q / INP, i = q - col * INP;
        int row = min(batch0 + col, batch - 1);
        sm.B[0][col * BPAD + HID + i] =
            __float2half(inputs[(size_t)row * (SEQ * INP) + i]);
    }

    // ---- load W_ext fragments into registers (single fp16), one-time
    uint32_t ahi[2][KT16][4];   // k16 tiles, k=0..63
    uint32_t ahi8[2][2];        // k8 tail, k=64..71
#pragma unroll
    for (int mt = 0; mt < 2; ++mt) {
        const int mbase = ((w << 1) | mt) << 4;
#pragma unroll
        for (int kt = 0; kt < KT16; ++kt) {
#pragma unroll
            for (int cp = 0; cp < 2; ++cp) {          // col pair: k+0/1 or k+8/9
#pragma unroll
                for (int rr = 0; rr < 2; ++rr) {      // row gid or gid+8
                    int m  = mbase + gid + rr * 8;
                    int k0 = kt * 16 + 2 * tig + cp * 8;
                    __half h0 = __float2half(wext(W_hh, W_ih, b_ih, b_hh, m, k0));
                    __half h1 = __float2half(wext(W_hh, W_ih, b_ih, b_hh, m, k0 + 1));
                    ahi[mt][kt][cp * 2 + rr] = pack_h2(h0, h1);
                }
            }
        }
        // k8 tail: k = 64 + 2*tig (+1)
#pragma unroll
        for (int rr = 0; rr < 2; ++rr) {
            int m  = mbase + gid + rr * 8;
            int k0 = 64 + 2 * tig;
            __half h0 = __float2half(wext(W_hh, W_ih, b_ih, b_hh, m, k0));
            __half h1 = __float2half(wext(W_hh, W_ih, b_ih, b_hh, m, k0 + 1));
            ahi8[mt][rr] = pack_h2(h0, h1);
        }
    }

    // x prefetch ownership: indices t and t+256 (< NB*INP = 280)
    const int  q1   = t + THREADS;
    const bool hq1  = q1 < NB * INP;
    const int  c0i  = t / INP,  i0 = t - c0i * INP;
    const int  c1i  = hq1 ? q1 / INP : 0, i1 = hq1 ? q1 - c1i * INP : 0;
    const float* xp0 = inputs + (size_t)min(batch0 + c0i, batch - 1) * (SEQ * INP) + i0;
    const float* xp1 = inputs + (size_t)min(batch0 + c1i, batch - 1) * (SEQ * INP) + i1;

    float cst[2 * NTL];
#pragma unroll
    for (int q = 0; q < 2 * NTL; ++q) cst[q] = 0.f;

    __syncthreads();

    for (int s = 0; s < SEQ; ++s) {
        // prefetch next x
        float xv0 = 0.f, xv1 = 0.f;
        const bool dox = (s + 1 < SEQ);
        if (dox) {
            xv0 = __ldg(xp0 + (size_t)(s + 1) * INP);
            if (hq1) xv1 = __ldg(xp1 + (size_t)(s + 1) * INP);
        }

        const __half* BH = sm.B[s & 1];
        __half*       WB = sm.B[(s + 1) & 1];

        float cacc[2][NTL][4];

        // B fragments, double-buffered across n-tiles
        uint32_t bh[2][KT16][2], b8h[2];

#define LOADFRAG(buf, nt)                                                     \
        {                                                                     \
            const int ncol = (nt) * 8 + gid;                                  \
            const uint32_t* colH = (const uint32_t*)(BH + ncol * BPAD);       \
            _Pragma("unroll")                                                 \
            for (int kt = 0; kt < KT16; ++kt) {                               \
                bh[buf][kt][0] = colH[kt * 8 + tig];                          \
                bh[buf][kt][1] = colH[kt * 8 + tig + 4];                      \
            }                                                                 \
            b8h[buf] = colH[32 + tig];                                        \
        }

        // Epilogue for one n-tile: cells (j=jm, col = nt*8 + 2tig + q)
#define EPILOGUE(nt)                                                          \
        {                                                                     \
            _Pragma("unroll")                                                 \
            for (int q = 0; q < 2; ++q) {                                     \
                const float gi = cacc[0][nt][q];                              \
                const float gf = cacc[0][nt][2 + q];                          \
                const float gg = cacc[1][nt][q];                              \
                const float go = cacc[1][nt][2 + q];                          \
                const float ig = sigmoid_f(gi);                               \
                const float fg = sigmoid_f(gf);                               \
                const float gt = tanh_f(gg);                                  \
                const float og = sigmoid_f(go);                               \
                const int  ci = (nt) * 2 + q;                                 \
                const float cn = fg * cst[ci] + ig * gt;                      \
                cst[ci] = cn;                                                 \
                const float hv = og * tanh_f(cn);                             \
                const int col = (nt) * 8 + 2 * tig + q;                       \
                WB[col * BPAD + jm] = __float2half(hv);                       \
            }                                                                 \
        }

        LOADFRAG(0, 0);
#pragma unroll
        for (int nt = 0; nt < NTL; ++nt) {
            const int cur = nt & 1, nxt = cur ^ 1;
            // pipeline: next tile's LDS issue before this tile's MMA burst
            if (nt + 1 < NTL) LOADFRAG(nxt, nt + 1);

#pragma unroll
            for (int mt = 0; mt < 2; ++mt)
#pragma unroll
                for (int q = 0; q < 4; ++q) cacc[mt][nt][q] = 0.f;

            // 1-term fp16: W*B; mt-interleaved (2 chains)
#pragma unroll
            for (int kt = 0; kt < KT16; ++kt) {
                mma16816(cacc[0][nt], ahi[0][kt], bh[cur][kt]);
                mma16816(cacc[1][nt], ahi[1][kt], bh[cur][kt]);
            }
            mma1688(cacc[0][nt], ahi8[0], b8h[cur]);
            mma1688(cacc[1][nt], ahi8[1], b8h[cur]);

            if (nt > 0) EPILOGUE(nt - 1);
        }
        EPILOGUE(NTL - 1);
#undef EPILOGUE
#undef LOADFRAG

        // stash next x into next-parity buffer
        if (dox) {
            WB[c0i * BPAD + HID + i0] = __float2half(xv0);
            if (hq1) WB[c1i * BPAD + HID + i1] = __float2half(xv1);
        }
        __syncthreads();
    }

    // ---- final FC + leaky ReLU; h(512) is in parity-0 buffer
    const __half* FH = sm.B[0];
    const float fw0 = fc_w[lane], fw1 = fc_w[lane + 32];
    const float fb  = fc_b[0];
#pragma unroll
    for (int q = 0; q < NTL; ++q) {
        const int col = w * NTL + q;
        float hA = __half2float(FH[col * BPAD + lane]);
        float hB = __half2float(FH[col * BPAD + lane + 32]);
        float p = hA * fw0 + hB * fw1;
#pragma unroll
        for (int off = 16; off > 0; off >>= 1)
            p += __shfl_xor_sync(0xffffffffu, p, off);
        if (lane == 0) {
            const int row = batch0 + col;
            if (row < batch) {
                const float v = p + fb;
                out[row] = (v >= 0.f) ? v : 0.01f * v;
            }
        }
    }
}

extern "C" void kernel_launch(void* const* d_in, const int* in_sizes, int n_in,
                              void* d_out, int out_size) {
    const float* inputs = (const float*)d_in[0];
    const float* W_ih   = (const float*)d_in[1];
    const float* W_hh   = (const float*)d_in[2];
    const float* b_ih   = (const float*)d_in[3];
    const float* b_hh   = (const float*)d_in[4];
    const float* fc_w   = (const float*)d_in[5];
    const float* fc_b   = (const float*)d_in[6];
    float*       out    = (float*)d_out;

    const int batch = in_sizes[0] / (SEQ * INP);      // 8192
    const int grid  = (batch + NB - 1) / NB;          // 147

    lstm_hmma_kernel<<<grid, THREADS>>>(inputs, W_ih, W_hh, b_ih, b_hh,
                                        fc_w, fc_b, out, batch);
}